// round 16
// baseline (speedup 1.0000x reference)
#include <cuda_runtime.h>
#include <cuda_fp16.h>
#include <cuda_pipeline.h>
#include <cuda.h>

// Problem constants (fixed by reference)
#define VOCAB      32000
#define EMBED_DIM  128
#define BATCH      32
#define MAX_TREES  512
#define NSEG       (BATCH * MAX_TREES)   // 16384

#define CONV_BLOCKS   4000               // blocks doing table conversion
#define BOUND_BLOCKS  65                 // blocks doing segment bounds

// TMA kernel geometry
#define TWARPS   4                       // warps (=segments) per block
#define RING     8                       // mbarrier ring slots per warp
#define SLOT_B   2048                    // 4 tokens x 512B per slot
#define DSMEM    (TWARPS * RING * SLOT_B + 1024)   // + alignment slack

// Scratch (allocation-free __device__ globals)
__device__ int g_seg_start[NSEG + 1];
// Packed interleaved fp16 tables: per token, 512B record =
//   [128 fp16 key row | 128 fp16 value row] = 32 uint4 (lane l owns uint4 l).
// Row 0 (PAD token) is exactly zero -> safe padding target.
__device__ __align__(1024) uint4 g_pack[VOCAB * 32];

// ---------------------------------------------------------------------------
// Kernel 0 (fused): blocks [0, CONV_BLOCKS) convert the f32 tables to packed
// fp16; remaining blocks binary-search segment boundaries.
// ---------------------------------------------------------------------------
__global__ void __launch_bounds__(256)
prep_kernel(const float4* __restrict__ C_hop,
            const float4* __restrict__ C_hop1,
            const int*    __restrict__ tree_ids, int n) {
    if (blockIdx.x < CONV_BLOCKS) {
        const int NT = VOCAB * 32;                 // 1,024,000 output uint4s
        int j = blockIdx.x * blockDim.x + threadIdx.x;
        if (j >= NT) return;
        const int r = j >> 5;                      // token row
        const int c = j & 31;                      // uint4 slot in 512B record
        const float4* src = (c < 16) ? C_hop : C_hop1;
        const int cc = c & 15;

        float4 a0 = __ldg(&src[r * 32 + 2 * cc]);
        float4 a1 = __ldg(&src[r * 32 + 2 * cc + 1]);

        union { __half2 h2[4]; uint4 u; } p;
        p.h2[0] = __floats2half2_rn(a0.x, a0.y);
        p.h2[1] = __floats2half2_rn(a0.z, a0.w);
        p.h2[2] = __floats2half2_rn(a1.x, a1.y);
        p.h2[3] = __floats2half2_rn(a1.z, a1.w);
        g_pack[j] = p.u;
    } else {
        int s = (blockIdx.x - CONV_BLOCKS) * blockDim.x + threadIdx.x;
        if (s > NSEG) return;
        int lo = 0, hi = n;
        while (lo < hi) {
            int mid = (lo + hi) >> 1;
            if (__ldg(&tree_ids[mid]) < s) lo = mid + 1;
            else hi = mid;
        }
        g_seg_start[s] = lo;
    }
}

// ---------------------------------------------------------------------------
// Helpers: packed f32x2 accumulate + fp16x8 adds + mbarrier/TMA primitives
// ---------------------------------------------------------------------------
__device__ __forceinline__ void addf32x2(unsigned long long& a, float2 f) {
    unsigned long long b;
    asm("mov.b64 %0, {%1, %2};" : "=l"(b) : "f"(f.x), "f"(f.y));
    asm("add.rn.f32x2 %0, %0, %1;" : "+l"(a) : "l"(b));
}
__device__ __forceinline__ float2 u64_to_f2(unsigned long long a) {
    float2 f;
    asm("mov.b64 {%0, %1}, %2;" : "=f"(f.x), "=f"(f.y) : "l"(a));
    return f;
}
__device__ __forceinline__ uint4 hadd2x4(uint4 a, uint4 b) {
    union U { uint4 u; __half2 h[4]; };
    U x, y, r; x.u = a; y.u = b;
    r.h[0] = __hadd2(x.h[0], y.h[0]);
    r.h[1] = __hadd2(x.h[1], y.h[1]);
    r.h[2] = __hadd2(x.h[2], y.h[2]);
    r.h[3] = __hadd2(x.h[3], y.h[3]);
    return r.u;
}
__device__ __forceinline__ void flush_set(unsigned long long acc[4], uint4 s) {
    union { uint4 u; __half2 h[4]; } c; c.u = s;
    addf32x2(acc[0], __half22float2(c.h[0]));
    addf32x2(acc[1], __half22float2(c.h[1]));
    addf32x2(acc[2], __half22float2(c.h[2]));
    addf32x2(acc[3], __half22float2(c.h[3]));
}
__device__ __forceinline__ void mbar_init(unsigned mb, unsigned cnt) {
    asm volatile("mbarrier.init.shared.b64 [%0], %1;" :: "r"(mb), "r"(cnt) : "memory");
}
__device__ __forceinline__ void mbar_expect_tx(unsigned mb, unsigned tx) {
    asm volatile("mbarrier.arrive.expect_tx.shared.b64 _, [%0], %1;" :: "r"(mb), "r"(tx) : "memory");
}
__device__ __forceinline__ void mbar_wait(unsigned mb, unsigned parity) {
    unsigned done;
    asm volatile(
        "{\n\t.reg .pred p;\n\t"
        "mbarrier.try_wait.parity.acquire.cta.shared::cta.b64 p, [%1], %2;\n\t"
        "selp.b32 %0, 1, 0, p;\n\t}"
        : "=r"(done) : "r"(mb), "r"(parity) : "memory");
    if (!done) {
        asm volatile(
            "{\n\t.reg .pred P1;\n\t"
            "W_%=:\n\t"
            "mbarrier.try_wait.parity.acquire.cta.shared::cta.b64 P1, [%0], %1, 0x989680;\n\t"
            "@P1 bra.uni D_%=;\n\t"
            "bra.uni W_%=;\n\t"
            "D_%=:\n\t}"
            :: "r"(mb), "r"(parity) : "memory");
    }
}
__device__ __forceinline__ void tma_row(unsigned dst, const CUtensorMap* tm,
                                        int y, unsigned mb) {
    asm volatile(
        "cp.async.bulk.tensor.2d.shared::cta.global.tile.mbarrier::complete_tx::bytes "
        "[%0], [%1, {%2, %3}], [%4];"
        :: "r"(dst), "l"(tm), "r"(0), "r"(y), "r"(mb) : "memory");
}
__device__ __forceinline__ uint4 lds128(unsigned a) {
    uint4 v;
    asm volatile("ld.shared.v4.u32 {%0,%1,%2,%3}, [%4];"
                 : "=r"(v.x), "=r"(v.y), "=r"(v.z), "=r"(v.w) : "r"(a));
    return v;
}

// ---------------------------------------------------------------------------
// Kernel 2 (TMA path): ONE warp per segment. Lane 0 issues 4 TMA row loads
// per 4-token group into an 8-slot smem ring; completion via per-slot
// mbarrier (expect_tx 2048). No per-lane gather addressing at all.
// Consumer: LDS.128 + HADD2 (2 rotating fp16 sets), f32x2 flush per 16 tok.
// ---------------------------------------------------------------------------
__global__ void __launch_bounds__(TWARPS * 32)
seg_sum_tma(const int* __restrict__ token_ids,
            float4*    __restrict__ out,
            const __grid_constant__ CUtensorMap tmap)
{
    __shared__ unsigned long long mbars[TWARPS][RING];
    extern __shared__ char dsm_raw[];

    const int w    = threadIdx.x >> 5;
    const int lane = threadIdx.x & 31;
    const int seg  = blockIdx.x * TWARPS + w;      // grid = NSEG/TWARPS

    unsigned dataw = ((unsigned)__cvta_generic_to_shared(dsm_raw) + 1023u) & ~1023u;
    dataw += (unsigned)w * (RING * SLOT_B);
    const unsigned mbar0 = (unsigned)__cvta_generic_to_shared(&mbars[w][0]);

    if (lane == 0) {
        #pragma unroll
        for (int s = 0; s < RING; s++) mbar_init(mbar0 + 8u * s, 1);
    }
    __syncwarp();

    const int beg = g_seg_start[seg];
    const int end = g_seg_start[seg + 1];
    const int cnt = end - beg;
    const int lim = (cnt + 3) & ~3;                // padded (token 0 = zero row)
    const int ngroups = lim >> 2;

    // Token-id window: cur = chunk cc, nxt = chunk cc+1 (32 tokens each).
    int cc = 0;
    auto fetchids = [&](int c) -> int {
        int pos = beg + (c << 5) + lane;
        return (pos < end) ? __ldg(&token_ids[pos]) : 0;
    };
    int cur = fetchids(0);
    int nxt = fetchids(1);

    auto issue = [&](int gi) {
        const int pos = gi << 2;
        const int c   = pos >> 5;
        if (c != cc) { cc = c; cur = nxt; nxt = fetchids(c + 1); }
        const int q  = pos & 31;
        int t0 = __shfl_sync(0xffffffffu, cur, q + 0);
        int t1 = __shfl_sync(0xffffffffu, cur, q + 1);
        int t2 = __shfl_sync(0xffffffffu, cur, q + 2);
        int t3 = __shfl_sync(0xffffffffu, cur, q + 3);
        if (lane == 0) {
            const unsigned s   = (unsigned)(gi & (RING - 1));
            const unsigned mb  = mbar0 + 8u * s;
            const unsigned dst = dataw + s * SLOT_B;
            mbar_expect_tx(mb, 4 * 512);
            tma_row(dst,        &tmap, t0, mb);
            tma_row(dst + 512,  &tmap, t1, mb);
            tma_row(dst + 1024, &tmap, t2, mb);
            tma_row(dst + 1536, &tmap, t3, mb);
        }
    };

    int gi = 0;
    for (; gi < ngroups && gi < RING; gi++) issue(gi);

    unsigned long long acc[4] = {0ull, 0ull, 0ull, 0ull};
    const uint4 z4 = make_uint4(0u, 0u, 0u, 0u);
    uint4 h0 = z4, h1 = z4;

    for (int g = 0; g < ngroups; g++) {
        const unsigned s = (unsigned)(g & (RING - 1));
        mbar_wait(mbar0 + 8u * s, (unsigned)((g >> 3) & 1));
        const unsigned base = dataw + s * SLOT_B + (unsigned)lane * 16u;
        uint4 r0 = lds128(base + 0);
        uint4 r1 = lds128(base + 512);
        uint4 r2 = lds128(base + 1024);
        uint4 r3 = lds128(base + 1536);
        if (gi < ngroups) { issue(gi); gi++; }

        h0 = hadd2x4(h0, r0);
        h1 = hadd2x4(h1, r1);
        h0 = hadd2x4(h0, r2);
        h1 = hadd2x4(h1, r3);
        if ((g & 3) == 3) {                        // flush every 16 tokens
            flush_set(acc, h0); flush_set(acc, h1);
            h0 = z4; h1 = z4;
        }
    }
    flush_set(acc, h0);
    flush_set(acc, h1);

    float2 f0 = u64_to_f2(acc[0]);
    float2 f1 = u64_to_f2(acc[1]);
    float2 f2 = u64_to_f2(acc[2]);
    float2 f3 = u64_to_f2(acc[3]);

    // lanes 0-15: key row floats [8*lane, 8*lane+8); lanes 16-31: value row.
    const int tbl = lane >> 4;
    const int col = lane & 15;
    float4* dst = &out[(((size_t)tbl * NSEG) + seg) * 32 + col * 2];
    dst[0] = make_float4(f0.x, f0.y, f1.x, f1.y);
    dst[1] = make_float4(f2.x, f2.y, f3.x, f3.y);
}

// ---------------------------------------------------------------------------
// Kernel 2 (fallback = proven R15 cp.async path, used if TMA setup fails)
// ---------------------------------------------------------------------------
__global__ void __launch_bounds__(128)
seg_sum_fb(const int* __restrict__ token_ids,
           float4*    __restrict__ out)
{
    __shared__ uint4 slots[4][4][4][32];

    const int w    = threadIdx.x >> 5;
    const int lane = threadIdx.x & 31;
    const int seg  = blockIdx.x * 4 + w;

    const int beg = g_seg_start[seg];
    const int end = g_seg_start[seg + 1];
    const int cnt = end - beg;
    const int lim = (cnt + 3) & ~3;

    int cc = 0;
    auto fetchids = [&](int c) -> int {
        int pos = beg + (c << 5) + lane;
        return (pos < end) ? __ldg(&token_ids[pos]) : 0;
    };
    int cur = fetchids(0);
    int nxt = fetchids(1);

    auto issue4 = [&](int pos) {
        if ((pos >> 5) != cc) { cc = pos >> 5; cur = nxt; nxt = fetchids(cc + 1); }
        const int q = pos & 31;
        const int s = (pos >> 2) & 3;
        int t0 = __shfl_sync(0xffffffffu, cur, q + 0);
        int t1 = __shfl_sync(0xffffffffu, cur, q + 1);
        int t2 = __shfl_sync(0xffffffffu, cur, q + 2);
        int t3 = __shfl_sync(0xffffffffu, cur, q + 3);
        __pipeline_memcpy_async(&slots[w][s][0][lane], &g_pack[t0 * 32 + lane], 16);
        __pipeline_memcpy_async(&slots[w][s][1][lane], &g_pack[t1 * 32 + lane], 16);
        __pipeline_memcpy_async(&slots[w][s][2][lane], &g_pack[t2 * 32 + lane], 16);
        __pipeline_memcpy_async(&slots[w][s][3][lane], &g_pack[t3 * 32 + lane], 16);
        __pipeline_commit();
    };

    #pragma unroll
    for (int p = 0; p < 4; p++) {
        if (p * 4 < lim) issue4(p * 4); else __pipeline_commit();
    }

    unsigned long long acc[4] = {0ull, 0ull, 0ull, 0ull};
    const uint4 z4 = make_uint4(0u, 0u, 0u, 0u);
    uint4 h0 = z4, h1 = z4;

    for (int u = 0; u < lim; u += 4) {
        __pipeline_wait_prior(3);
        const int s = (u >> 2) & 3;
        uint4 r0 = slots[w][s][0][lane];
        uint4 r1 = slots[w][s][1][lane];
        uint4 r2 = slots[w][s][2][lane];
        uint4 r3 = slots[w][s][3][lane];
        if (u + 16 < lim) issue4(u + 16); else __pipeline_commit();

        h0 = hadd2x4(h0, r0);
        h1 = hadd2x4(h1, r1);
        h0 = hadd2x4(h0, r2);
        h1 = hadd2x4(h1, r3);
        if ((u & 12) == 12) {
            flush_set(acc, h0); flush_set(acc, h1);
            h0 = z4; h1 = z4;
        }
    }
    flush_set(acc, h0);
    flush_set(acc, h1);

    float2 f0 = u64_to_f2(acc[0]);
    float2 f1 = u64_to_f2(acc[1]);
    float2 f2 = u64_to_f2(acc[2]);
    float2 f3 = u64_to_f2(acc[3]);

    const int tbl = lane >> 4;
    const int col = lane & 15;
    float4* dst = &out[(((size_t)tbl * NSEG) + seg) * 32 + col * 2];
    dst[0] = make_float4(f0.x, f0.y, f1.x, f1.y);
    dst[1] = make_float4(f2.x, f2.y, f3.x, f3.y);
}

// ---------------------------------------------------------------------------
// Launch
// ---------------------------------------------------------------------------
typedef CUresult (*EncodeFn)(CUtensorMap*, CUtensorMapDataType, cuuint32_t,
                             void*, const cuuint64_t*, const cuuint64_t*,
                             const cuuint32_t*, const cuuint32_t*,
                             CUtensorMapInterleave, CUtensorMapSwizzle,
                             CUtensorMapL2promotion, CUtensorMapFloatOOBfill);

extern "C" void kernel_launch(void* const* d_in, const int* in_sizes, int n_in,
                              void* d_out, int out_size) {
    const int*    token_ids = (const int*)   d_in[0];
    const int*    tree_ids  = (const int*)   d_in[1];
    const float4* C_hop     = (const float4*)d_in[2];
    const float4* C_hop1    = (const float4*)d_in[3];
    float4*       out       = (float4*)      d_out;

    const int n = in_sizes[0];  // TOTAL_TOKENS

    // Kernel 0: fused table conversion + segment bounds
    prep_kernel<<<CONV_BLOCKS + BOUND_BLOCKS, 256>>>(C_hop, C_hop1, tree_ids, n);

    // Try TMA path: encode a tensormap for g_pack viewed as [VOCAB, 128 u32].
    bool ok = false;
    CUtensorMap tmap;
    do {
        void* sym = nullptr;
        if (cudaGetSymbolAddress(&sym, g_pack) != cudaSuccess || !sym) break;

        void* fn = nullptr;
        cudaDriverEntryPointQueryResult qr;
#if CUDART_VERSION >= 12050
        if (cudaGetDriverEntryPointByVersion("cuTensorMapEncodeTiled", &fn,
                                             12000, cudaEnableDefault, &qr)
            != cudaSuccess || !fn) break;
#else
        if (cudaGetDriverEntryPoint("cuTensorMapEncodeTiled", &fn,
                                    cudaEnableDefault, &qr)
            != cudaSuccess || !fn) break;
#endif
        EncodeFn enc = (EncodeFn)fn;
        cuuint64_t dims[2]    = {128, VOCAB};      // 128 u32 per row, VOCAB rows
        cuuint64_t strides[1] = {512};             // row pitch bytes
        cuuint32_t box[2]     = {128, 1};          // one 512B row per load
        cuuint32_t es[2]      = {1, 1};
        if (enc(&tmap, CU_TENSOR_MAP_DATA_TYPE_UINT32, 2, sym,
                dims, strides, box, es,
                CU_TENSOR_MAP_INTERLEAVE_NONE, CU_TENSOR_MAP_SWIZZLE_NONE,
                CU_TENSOR_MAP_L2_PROMOTION_L2_128B,
                CU_TENSOR_MAP_FLOAT_OOB_FILL_NONE) != CUDA_SUCCESS) break;

        if (cudaFuncSetAttribute(seg_sum_tma,
                                 cudaFuncAttributeMaxDynamicSharedMemorySize,
                                 DSMEM) != cudaSuccess) break;
        ok = true;
    } while (0);

    if (ok) {
        seg_sum_tma<<<NSEG / TWARPS, TWARPS * 32, DSMEM>>>(token_ids, out, tmap);
    } else {
        seg_sum_fb<<<NSEG / 4, 128>>>(token_ids, out);
    }
}

// round 17
// speedup vs baseline: 1.2972x; 1.2972x over previous
#include <cuda_runtime.h>
#include <cuda_fp16.h>

// Problem constants (fixed by reference)
#define VOCAB      32000
#define EMBED_DIM  128
#define BATCH      32
#define MAX_TREES  512
#define NSEG       (BATCH * MAX_TREES)   // 16384

#define CONV_BLOCKS   4000               // blocks doing table conversion
#define BOUND_BLOCKS  65                 // blocks doing segment bounds

// Warp-specialized gather geometry
#define GSEGS   4                        // segments per block
#define RING    8                        // ring slots per segment
#define SLOT_B  2048                     // 4 tokens x 512B per slot
#define DSM     (GSEGS * RING * SLOT_B + 1024)

// Scratch (allocation-free __device__ globals)
__device__ int g_seg_start[NSEG + 1];
// Packed interleaved fp16 tables: per token, 512B record =
//   [128 fp16 key row | 128 fp16 value row] = 32 uint4 (lane l owns uint4 l).
// Row 0 (PAD token) is exactly zero -> safe padding target.
__device__ __align__(1024) uint4 g_pack[VOCAB * 32];

// ---------------------------------------------------------------------------
// Kernel 0 (fused): blocks [0, CONV_BLOCKS) convert the f32 tables to packed
// fp16; remaining blocks binary-search segment boundaries.
// ---------------------------------------------------------------------------
__global__ void __launch_bounds__(256)
prep_kernel(const float4* __restrict__ C_hop,
            const float4* __restrict__ C_hop1,
            const int*    __restrict__ tree_ids, int n) {
    if (blockIdx.x < CONV_BLOCKS) {
        const int NT = VOCAB * 32;                 // 1,024,000 output uint4s
        int j = blockIdx.x * blockDim.x + threadIdx.x;
        if (j >= NT) return;
        const int r = j >> 5;                      // token row
        const int c = j & 31;                      // uint4 slot in 512B record
        const float4* src = (c < 16) ? C_hop : C_hop1;
        const int cc = c & 15;

        float4 a0 = __ldg(&src[r * 32 + 2 * cc]);
        float4 a1 = __ldg(&src[r * 32 + 2 * cc + 1]);

        union { __half2 h2[4]; uint4 u; } p;
        p.h2[0] = __floats2half2_rn(a0.x, a0.y);
        p.h2[1] = __floats2half2_rn(a0.z, a0.w);
        p.h2[2] = __floats2half2_rn(a1.x, a1.y);
        p.h2[3] = __floats2half2_rn(a1.z, a1.w);
        g_pack[j] = p.u;
    } else {
        int s = (blockIdx.x - CONV_BLOCKS) * blockDim.x + threadIdx.x;
        if (s > NSEG) return;
        int lo = 0, hi = n;
        while (lo < hi) {
            int mid = (lo + hi) >> 1;
            if (__ldg(&tree_ids[mid]) < s) lo = mid + 1;
            else hi = mid;
        }
        g_seg_start[s] = lo;
    }
}

// ---------------------------------------------------------------------------
// Helpers
// ---------------------------------------------------------------------------
__device__ __forceinline__ void addf32x2(unsigned long long& a, float2 f) {
    unsigned long long b;
    asm("mov.b64 %0, {%1, %2};" : "=l"(b) : "f"(f.x), "f"(f.y));
    asm("add.rn.f32x2 %0, %0, %1;" : "+l"(a) : "l"(b));
}
__device__ __forceinline__ float2 u64_to_f2(unsigned long long a) {
    float2 f;
    asm("mov.b64 {%0, %1}, %2;" : "=f"(f.x), "=f"(f.y) : "l"(a));
    return f;
}
__device__ __forceinline__ uint4 hadd2x4(uint4 a, uint4 b) {
    union U { uint4 u; __half2 h[4]; };
    U x, y, r; x.u = a; y.u = b;
    r.h[0] = __hadd2(x.h[0], y.h[0]);
    r.h[1] = __hadd2(x.h[1], y.h[1]);
    r.h[2] = __hadd2(x.h[2], y.h[2]);
    r.h[3] = __hadd2(x.h[3], y.h[3]);
    return r.u;
}
__device__ __forceinline__ void flush_set(unsigned long long acc[4], uint4 s) {
    union { uint4 u; __half2 h[4]; } c; c.u = s;
    addf32x2(acc[0], __half22float2(c.h[0]));
    addf32x2(acc[1], __half22float2(c.h[1]));
    addf32x2(acc[2], __half22float2(c.h[2]));
    addf32x2(acc[3], __half22float2(c.h[3]));
}
__device__ __forceinline__ void mbar_init(unsigned mb, unsigned cnt) {
    asm volatile("mbarrier.init.shared.b64 [%0], %1;" :: "r"(mb), "r"(cnt) : "memory");
}
__device__ __forceinline__ void mbar_arrive(unsigned mb) {
    asm volatile("mbarrier.arrive.shared.b64 _, [%0];" :: "r"(mb) : "memory");
}
__device__ __forceinline__ void mbar_wait(unsigned mb, unsigned parity) {
    unsigned done;
    asm volatile(
        "{\n\t.reg .pred p;\n\t"
        "mbarrier.try_wait.parity.acquire.cta.shared::cta.b64 p, [%1], %2;\n\t"
        "selp.b32 %0, 1, 0, p;\n\t}"
        : "=r"(done) : "r"(mb), "r"(parity) : "memory");
    if (!done) {
        asm volatile(
            "{\n\t.reg .pred P1;\n\t"
            "W_%=:\n\t"
            "mbarrier.try_wait.parity.acquire.cta.shared::cta.b64 P1, [%0], %1, 0x989680;\n\t"
            "@P1 bra.uni D_%=;\n\t"
            "bra.uni W_%=;\n\t"
            "D_%=:\n\t}"
            :: "r"(mb), "r"(parity) : "memory");
    }
}
__device__ __forceinline__ void cpa16(unsigned dst, const void* src) {
    asm volatile("cp.async.cg.shared.global [%0], [%1], 16;"
                 :: "r"(dst), "l"(src) : "memory");
}
__device__ __forceinline__ void cpa_mbar_arrive(unsigned mb) {
    asm volatile("cp.async.mbarrier.arrive.noinc.shared.b64 [%0];"
                 :: "r"(mb) : "memory");
}
__device__ __forceinline__ uint4 lds128(unsigned a) {
    uint4 v;
    asm volatile("ld.shared.v4.u32 {%0,%1,%2,%3}, [%4];"
                 : "=r"(v.x), "=r"(v.y), "=r"(v.z), "=r"(v.w) : "r"(a));
    return v;
}

// ---------------------------------------------------------------------------
// Kernel 2: warp-specialized gather. Per segment: producer warp streams
// cp.asyncs into an 8-slot x 2KB smem ring (full-barrier via
// cp.async.mbarrier.arrive.noinc, count 32); consumer warp LDS+HADD2s and
// releases slots via an empty-barrier. Ring stays full independent of
// consumer pace -> ~192KB of gathers in flight per SM.
// ---------------------------------------------------------------------------
__global__ void __launch_bounds__(GSEGS * 64)
seg_sum_ws(const int* __restrict__ token_ids,
           float4*    __restrict__ out)        // [2][NSEG][32] float4
{
    __shared__ unsigned long long full_mb[GSEGS][RING];
    __shared__ unsigned long long empty_mb[GSEGS][RING];
    extern __shared__ char dsm_raw[];

    const int w    = threadIdx.x >> 5;         // 0..7
    const int lane = threadIdx.x & 31;
    const int slot = w & (GSEGS - 1);          // segment slot 0..3
    const int role = w >> 2;                   // 0 = producer, 1 = consumer
    const int seg  = blockIdx.x * GSEGS + slot;

    unsigned dbase = ((unsigned)__cvta_generic_to_shared(dsm_raw) + 1023u) & ~1023u;
    dbase += (unsigned)slot * (RING * SLOT_B);
    const unsigned fmb0 = (unsigned)__cvta_generic_to_shared(&full_mb[slot][0]);
    const unsigned emb0 = (unsigned)__cvta_generic_to_shared(&empty_mb[slot][0]);

    if (threadIdx.x == 0) {
        for (int i = 0; i < GSEGS; i++)
            for (int s = 0; s < RING; s++) {
                mbar_init((unsigned)__cvta_generic_to_shared(&full_mb[i][s]), 32);
                mbar_init((unsigned)__cvta_generic_to_shared(&empty_mb[i][s]), 32);
            }
    }
    __syncthreads();

    const int beg = g_seg_start[seg];
    const int end = g_seg_start[seg + 1];
    const int cnt = end - beg;
    const int lim = (cnt + 3) & ~3;            // padded (token 0 = zero row)
    const int ngroups = lim >> 2;

    if (role == 0) {
        // ---------------- PRODUCER ----------------
        int cc = 0;
        auto fetchids = [&](int c) -> int {
            int pos = beg + (c << 5) + lane;
            return (pos < end) ? __ldg(&token_ids[pos]) : 0;
        };
        int cur = fetchids(0);
        int nxt = fetchids(1);

        for (int gi = 0; gi < ngroups; gi++) {
            const int s = gi & (RING - 1);
            if (gi >= RING)
                mbar_wait(emb0 + 8u * s, (unsigned)(((gi >> 3) + 1) & 1));

            const int pos = gi << 2;
            const int c   = pos >> 5;
            if (c != cc) { cc = c; cur = nxt; nxt = fetchids(c + 1); }
            const int q = pos & 31;
            int t0 = __shfl_sync(0xffffffffu, cur, q + 0);
            int t1 = __shfl_sync(0xffffffffu, cur, q + 1);
            int t2 = __shfl_sync(0xffffffffu, cur, q + 2);
            int t3 = __shfl_sync(0xffffffffu, cur, q + 3);

            const unsigned dst = dbase + (unsigned)s * SLOT_B + (unsigned)lane * 16u;
            cpa16(dst,         &g_pack[t0 * 32 + lane]);
            cpa16(dst + 512,   &g_pack[t1 * 32 + lane]);
            cpa16(dst + 1024,  &g_pack[t2 * 32 + lane]);
            cpa16(dst + 1536,  &g_pack[t3 * 32 + lane]);
            cpa_mbar_arrive(fmb0 + 8u * s);
        }
        asm volatile("cp.async.wait_all;" ::: "memory");
    } else {
        // ---------------- CONSUMER ----------------
        unsigned long long acc[4] = {0ull, 0ull, 0ull, 0ull};
        const uint4 z4 = make_uint4(0u, 0u, 0u, 0u);
        uint4 h0 = z4, h1 = z4;

        for (int g = 0; g < ngroups; g++) {
            const int s = g & (RING - 1);
            mbar_wait(fmb0 + 8u * s, (unsigned)((g >> 3) & 1));
            const unsigned base = dbase + (unsigned)s * SLOT_B + (unsigned)lane * 16u;
            uint4 r0 = lds128(base + 0);
            uint4 r1 = lds128(base + 512);
            uint4 r2 = lds128(base + 1024);
            uint4 r3 = lds128(base + 1536);

            h0 = hadd2x4(h0, r0);
            h1 = hadd2x4(h1, r1);
            h0 = hadd2x4(h0, r2);
            h1 = hadd2x4(h1, r3);
            // hadds consumed the LDS results -> slot reads complete; release.
            mbar_arrive(emb0 + 8u * s);

            if ((g & 3) == 3) {                // flush every 16 tokens
                flush_set(acc, h0); flush_set(acc, h1);
                h0 = z4; h1 = z4;
            }
        }
        flush_set(acc, h0);
        flush_set(acc, h1);

        float2 f0 = u64_to_f2(acc[0]);
        float2 f1 = u64_to_f2(acc[1]);
        float2 f2 = u64_to_f2(acc[2]);
        float2 f3 = u64_to_f2(acc[3]);

        // lanes 0-15: key row floats [8*lane,8*lane+8); lanes 16-31: value.
        const int tbl = lane >> 4;
        const int col = lane & 15;
        float4* dst = &out[(((size_t)tbl * NSEG) + seg) * 32 + col * 2];
        dst[0] = make_float4(f0.x, f0.y, f1.x, f1.y);
        dst[1] = make_float4(f2.x, f2.y, f3.x, f3.y);
    }
}

// ---------------------------------------------------------------------------
// Launch
// ---------------------------------------------------------------------------
extern "C" void kernel_launch(void* const* d_in, const int* in_sizes, int n_in,
                              void* d_out, int out_size) {
    const int*    token_ids = (const int*)   d_in[0];
    const int*    tree_ids  = (const int*)   d_in[1];
    const float4* C_hop     = (const float4*)d_in[2];
    const float4* C_hop1    = (const float4*)d_in[3];
    float4*       out       = (float4*)      d_out;

    const int n = in_sizes[0];  // TOTAL_TOKENS

    // Kernel 0: fused table conversion + segment bounds
    prep_kernel<<<CONV_BLOCKS + BOUND_BLOCKS, 256>>>(C_hop, C_hop1, tree_ids, n);

    // Kernel 2: warp-specialized gather, 4 segments x 2 warps per block
    static bool attr_set = false;
    cudaFuncSetAttribute(seg_sum_ws,
                         cudaFuncAttributeMaxDynamicSharedMemorySize, DSM);
    (void)attr_set;
    seg_sum_ws<<<NSEG / GSEGS, GSEGS * 64, DSM>>>(token_ids, out);
}